// round 2
// baseline (speedup 1.0000x reference)
#include <cuda_runtime.h>
#include <cstdint>

// Problem constants
#define BB 2
#define TT 2048
#define DD 1024
#define HH 16
#define HD 64
#define M_ROWS (BB * TT)        // 4096
#define QKV_N (3 * DD)          // 3072

// Scratch (allocation-free rule: __device__ globals)
__device__ float g_qkv[(size_t)M_ROWS * QKV_N]; // [B*T, 3D]
__device__ float g_z[(size_t)M_ROWS * DD];      // [B*T, D]

// ---------------------------------------------------------------------------
// SGEMM NT: C[M,N] = A[M,K] * B[N,K]^T   (A,B row-major, K contiguous)
// 128x128 tile, BK=16, 256 threads, 8x8 per thread (2x2 float4 quadrants)
// ---------------------------------------------------------------------------
__global__ __launch_bounds__(256) void sgemm_nt(const float* __restrict__ A,
                                                const float* __restrict__ B,
                                                float* __restrict__ C,
                                                int M, int N, int K)
{
    const int BM = 128, BN = 128, BK = 16;
    __shared__ float As[BK][BM + 4];   // [k][m]
    __shared__ float Bs[BK][BN + 4];   // [k][n]

    const int tid = threadIdx.x;
    const int tx = tid & 15;           // col group
    const int ty = tid >> 4;           // row group
    const int lrow = tid >> 2;         // 0..63
    const int lcol = (tid & 3) * 4;    // 0,4,8,12

    const float* Ab = A + (size_t)blockIdx.y * BM * K;
    const float* Bb = B + (size_t)blockIdx.x * BN * K;

    float acc[8][8];
#pragma unroll
    for (int i = 0; i < 8; i++)
#pragma unroll
        for (int j = 0; j < 8; j++) acc[i][j] = 0.f;

    for (int k0 = 0; k0 < K; k0 += BK) {
#pragma unroll
        for (int half = 0; half < 2; half++) {
            int r = lrow + half * 64;
            float4 va = *(const float4*)(Ab + (size_t)r * K + k0 + lcol);
            As[lcol + 0][r] = va.x; As[lcol + 1][r] = va.y;
            As[lcol + 2][r] = va.z; As[lcol + 3][r] = va.w;
            float4 vb = *(const float4*)(Bb + (size_t)r * K + k0 + lcol);
            Bs[lcol + 0][r] = vb.x; Bs[lcol + 1][r] = vb.y;
            Bs[lcol + 2][r] = vb.z; Bs[lcol + 3][r] = vb.w;
        }
        __syncthreads();

#pragma unroll
        for (int k = 0; k < BK; k++) {
            float a[8], b[8];
            float4 a0 = *(const float4*)&As[k][ty * 4];
            float4 a1 = *(const float4*)&As[k][64 + ty * 4];
            a[0]=a0.x; a[1]=a0.y; a[2]=a0.z; a[3]=a0.w;
            a[4]=a1.x; a[5]=a1.y; a[6]=a1.z; a[7]=a1.w;
            float4 b0 = *(const float4*)&Bs[k][tx * 4];
            float4 b1 = *(const float4*)&Bs[k][64 + tx * 4];
            b[0]=b0.x; b[1]=b0.y; b[2]=b0.z; b[3]=b0.w;
            b[4]=b1.x; b[5]=b1.y; b[6]=b1.z; b[7]=b1.w;
#pragma unroll
            for (int i = 0; i < 8; i++)
#pragma unroll
                for (int j = 0; j < 8; j++) acc[i][j] += a[i] * b[j];
        }
        __syncthreads();
    }

    // Write back: rows {ty*4+i, 64+ty*4+i}, cols {tx*4.., 64+tx*4..}
    float* Cb = C + (size_t)(blockIdx.y * BM) * N + blockIdx.x * BN;
#pragma unroll
    for (int rh = 0; rh < 2; rh++) {
#pragma unroll
        for (int i = 0; i < 4; i++) {
            int r = rh * 64 + ty * 4 + i;
            int ai = rh * 4 + i;
#pragma unroll
            for (int ch = 0; ch < 2; ch++) {
                float4 v;
                v.x = acc[ai][ch * 4 + 0]; v.y = acc[ai][ch * 4 + 1];
                v.z = acc[ai][ch * 4 + 2]; v.w = acc[ai][ch * 4 + 3];
                *(float4*)(Cb + (size_t)r * N + ch * 64 + tx * 4) = v;
            }
        }
    }
}

// ---------------------------------------------------------------------------
// Flash attention, fp32, causal. One block = 64 query rows of one (b,h).
// 256 threads = 16 row-groups x 16 col-groups; 4x4 micro-tile per thread in
// both QK^T and PV phases (balances LDS 128B/cyc against 2 FMA-inst/cyc).
// smem: Q[64][65], KV[64][65] (K then V reuse), P[64][68]  = 50688 B dynamic.
// ---------------------------------------------------------------------------
#define QS_STR 65
#define PS_STR 68
#define FLASH_SMEM ((2 * 64 * QS_STR + 64 * PS_STR) * 4)

__global__ __launch_bounds__(256) void flash_attn(const float* __restrict__ qkv,
                                                  float* __restrict__ z)
{
    extern __shared__ float sm[];
    float* Qs  = sm;                    // [64][65]
    float* KVs = sm + 64 * QS_STR;      // [64][65]
    float* Ps  = sm + 2 * 64 * QS_STR;  // [64][68]

    const int qt = blockIdx.x;   // query tile (0..31)
    const int h  = blockIdx.y;
    const int b  = blockIdx.z;
    const int tid = threadIdx.x;
    const int rg = tid >> 4;     // 0..15: rows rg*4..rg*4+3
    const int cg = tid & 15;     // 0..15: cols cg+16*{0..3}
    const int lr = tid >> 2;     // loader row 0..63
    const int lc = (tid & 3) * 16;
    const int q0 = qt * 64;
    const size_t rs = QKV_N;     // qkv row stride

    // Load Q tile, pre-scaled by 1/sqrt(HD) = 0.125
    {
        const float* src = qkv + ((size_t)(b * TT + q0 + lr)) * rs + h * HD + lc;
#pragma unroll
        for (int i = 0; i < 4; i++) {
            float4 v = *(const float4*)(src + i * 4);
            float* d = &Qs[lr * QS_STR + lc + i * 4];
            d[0] = v.x * 0.125f; d[1] = v.y * 0.125f;
            d[2] = v.z * 0.125f; d[3] = v.w * 0.125f;
        }
    }

    float m_[4], l_[4], o_[4][4];
#pragma unroll
    for (int i = 0; i < 4; i++) {
        m_[i] = -1e30f; l_[i] = 0.f;
#pragma unroll
        for (int c = 0; c < 4; c++) o_[i][c] = 0.f;
    }

    for (int kt = 0; kt <= qt; kt++) {
        const int k0 = kt * 64;
        __syncthreads();   // Qs ready / previous PV reads done
        // Load K tile
        {
            const float* src = qkv + ((size_t)(b * TT + k0 + lr)) * rs + DD + h * HD + lc;
#pragma unroll
            for (int i = 0; i < 4; i++) {
                float4 v = *(const float4*)(src + i * 4);
                float* d = &KVs[lr * QS_STR + lc + i * 4];
                d[0] = v.x; d[1] = v.y; d[2] = v.z; d[3] = v.w;
            }
        }
        __syncthreads();

        // S = Q K^T  (thread: 4 rows x 4 cols)
        float s[4][4];
#pragma unroll
        for (int i = 0; i < 4; i++)
#pragma unroll
            for (int j = 0; j < 4; j++) s[i][j] = 0.f;

#pragma unroll 4
        for (int d = 0; d < 64; d++) {
            float qa[4], kb[4];
#pragma unroll
            for (int i = 0; i < 4; i++) qa[i] = Qs[(rg * 4 + i) * QS_STR + d];
#pragma unroll
            for (int j = 0; j < 4; j++) kb[j] = KVs[(cg + 16 * j) * QS_STR + d];
#pragma unroll
            for (int i = 0; i < 4; i++)
#pragma unroll
                for (int j = 0; j < 4; j++) s[i][j] += qa[i] * kb[j];
        }

        // Causal mask on diagonal tile
        if (kt == qt) {
#pragma unroll
            for (int i = 0; i < 4; i++)
#pragma unroll
                for (int j = 0; j < 4; j++)
                    if (cg + 16 * j > rg * 4 + i) s[i][j] = -1e30f;
        }

        // Online softmax (per-row state replicated across the 16 cg lanes)
#pragma unroll
        for (int i = 0; i < 4; i++) {
            float mx = fmaxf(fmaxf(s[i][0], s[i][1]), fmaxf(s[i][2], s[i][3]));
#pragma unroll
            for (int off = 1; off < 16; off <<= 1)
                mx = fmaxf(mx, __shfl_xor_sync(0xffffffffu, mx, off));
            float mnew = fmaxf(m_[i], mx);
            float alpha = __expf(m_[i] - mnew);
            float psum = 0.f;
#pragma unroll
            for (int j = 0; j < 4; j++) {
                float p = __expf(s[i][j] - mnew);
                s[i][j] = p;
                psum += p;
            }
#pragma unroll
            for (int off = 1; off < 16; off <<= 1)
                psum += __shfl_xor_sync(0xffffffffu, psum, off);
            l_[i] = l_[i] * alpha + psum;
            m_[i] = mnew;
#pragma unroll
            for (int c = 0; c < 4; c++) o_[i][c] *= alpha;
#pragma unroll
            for (int j = 0; j < 4; j++)
                Ps[(rg * 4 + i) * PS_STR + cg + 16 * j] = s[i][j];
        }
        __syncthreads();   // K reads done + P complete

        // Load V tile (reuse KVs)
        {
            const float* src = qkv + ((size_t)(b * TT + k0 + lr)) * rs + 2 * DD + h * HD + lc;
#pragma unroll
            for (int i = 0; i < 4; i++) {
                float4 v = *(const float4*)(src + i * 4);
                float* d = &KVs[lr * QS_STR + lc + i * 4];
                d[0] = v.x; d[1] = v.y; d[2] = v.z; d[3] = v.w;
            }
        }
        __syncthreads();

        // O += P V  (thread: 4 rows x 4 hd, hd = cg + 16*c)
#pragma unroll 4
        for (int j = 0; j < 64; j++) {
            float pa[4], vb[4];
#pragma unroll
            for (int i = 0; i < 4; i++) pa[i] = Ps[(rg * 4 + i) * PS_STR + j];
#pragma unroll
            for (int c = 0; c < 4; c++) vb[c] = KVs[j * QS_STR + cg + 16 * c];
#pragma unroll
            for (int i = 0; i < 4; i++)
#pragma unroll
                for (int c = 0; c < 4; c++) o_[i][c] += pa[i] * vb[c];
        }
    }

    // Normalize and write z[b, q, h*64 + hd]
#pragma unroll
    for (int i = 0; i < 4; i++) {
        float inv_l = 1.f / l_[i];
        size_t row = (size_t)(b * TT + q0 + rg * 4 + i) * DD + h * HD;
#pragma unroll
        for (int c = 0; c < 4; c++)
            z[row + cg + 16 * c] = o_[i][c] * inv_l;
    }
}

// ---------------------------------------------------------------------------
extern "C" void kernel_launch(void* const* d_in, const int* in_sizes, int n_in,
                              void* d_out, int out_size)
{
    const float* X    = (const float*)d_in[0];
    const float* Wqkv = (const float*)d_in[1];
    const float* Wout = (const float*)d_in[2];
    float* out = (float*)d_out;

    float* qkv; float* z;
    cudaGetSymbolAddress((void**)&qkv, g_qkv);
    cudaGetSymbolAddress((void**)&z, g_z);

    cudaFuncSetAttribute(flash_attn, cudaFuncAttributeMaxDynamicSharedMemorySize,
                         FLASH_SMEM);

    // 1) qkv = X @ W_qkv^T : [4096,1024] x [3072,1024]^T
    sgemm_nt<<<dim3(QKV_N / 128, M_ROWS / 128), 256>>>(X, Wqkv, qkv,
                                                       M_ROWS, QKV_N, DD);
    // 2) causal flash attention -> z
    flash_attn<<<dim3(TT / 64, HH, BB), 256, FLASH_SMEM>>>(qkv, z);
    // 3) out = z @ W_out^T : [4096,1024] x [1024,1024]^T
    sgemm_nt<<<dim3(DD / 128, M_ROWS / 128), 256>>>(z, Wout, out,
                                                    M_ROWS, DD, DD);
}